// round 2
// baseline (speedup 1.0000x reference)
#include <cuda_runtime.h>
#include <math.h>

#define NN 131072
#define DD 256
#define KK 1024
#define EPSV 1e-5f
#define DECAYV 0.99f

// ---- scratch (no allocations allowed) ----
__device__ float g_xnorm[NN];
__device__ float g_enorm[KK];
__device__ int   g_idx[NN];
__device__ int   g_counts[KK];
__device__ int   g_offsets[KK];
__device__ int   g_cursor[KK];
__device__ int   g_bucket[NN];
__device__ float g_ncs[KK];
__device__ float g_ntotal;
__device__ float g_mse;
__device__ float g_ortho;

// ---------------------------------------------------------------------------
__global__ void k_init() {
    int t = blockIdx.x * blockDim.x + threadIdx.x;
    if (t < KK) { g_counts[t] = 0; g_cursor[t] = 0; }
    if (t == 0) { g_mse = 0.f; g_ortho = 0.f; }
}

// one warp per row: row norms for inputs (N rows) then embedding (K rows)
__global__ __launch_bounds__(256) void k_norms(const float* __restrict__ flat,
                                               const float* __restrict__ emb) {
    int warp = (blockIdx.x * blockDim.x + threadIdx.x) >> 5;
    int lane = threadIdx.x & 31;
    if (warp >= NN + KK) return;
    const float4* p4 = (warp < NN)
        ? (const float4*)(flat + (size_t)warp * DD)
        : (const float4*)(emb + (size_t)(warp - NN) * DD);
    float s = 0.f;
#pragma unroll
    for (int c = 0; c < 2; c++) {
        float4 v = p4[lane + 32 * c];
        s += v.x * v.x + v.y * v.y + v.z * v.z + v.w * v.w;
    }
#pragma unroll
    for (int o = 16; o; o >>= 1) s += __shfl_xor_sync(0xffffffffu, s, o);
    if (lane == 0) {
        if (warp < NN) g_xnorm[warp] = s;
        else           g_enorm[warp - NN] = s;
    }
}

// ---------------------------------------------------------------------------
// Main kernel: for each input row, argmin_k of (||x||^2 + ||e_k||^2 - 2 x.e_k)
// Tiled SGEMM-style: block = 64 rows x all 1024 codes (in 16 chunks of 64),
// 256 threads as 16x16, 4x4 micro-tile, smem tiles 64x64 (+1 pad, conflict-free).
__global__ __launch_bounds__(256) void k_argmin(const float* __restrict__ flat,
                                                const float* __restrict__ emb,
                                                float* __restrict__ out_idx) {
    __shared__ float As[64][65];
    __shared__ float Bs[64][65];
    __shared__ float rv[64][16];
    __shared__ int   ri[64][16];

    int tid = threadIdx.x;
    int tx = tid & 15, ty = tid >> 4;
    int tx4 = tx * 4, ty4 = ty * 4;
    int rowbase = blockIdx.x * 64;

    float xn[4], best[4];
    int bidx[4];
#pragma unroll
    for (int i = 0; i < 4; i++) {
        xn[i] = g_xnorm[rowbase + ty4 + i];
        best[i] = 3.4e38f;
        bidx[i] = 0;
    }

    const float4* flat4 = (const float4*)flat;
    const float4* emb4  = (const float4*)emb;

    for (int kc = 0; kc < 16; kc++) {
        float acc[4][4];
#pragma unroll
        for (int i = 0; i < 4; i++)
#pragma unroll
            for (int j = 0; j < 4; j++) acc[i][j] = 0.f;

        for (int dc = 0; dc < 4; dc++) {
            // cooperative load of A tile (64 rows x 64 dims) and B tile
#pragma unroll
            for (int s = 0; s < 4; s++) {
                int i = s * 256 + tid;
                int r = i >> 4, c = i & 15;
                float4 va = flat4[(size_t)(rowbase + r) * 64 + dc * 16 + c];
                As[r][c * 4 + 0] = va.x; As[r][c * 4 + 1] = va.y;
                As[r][c * 4 + 2] = va.z; As[r][c * 4 + 3] = va.w;
                float4 vb = emb4[(size_t)(kc * 64 + r) * 64 + dc * 16 + c];
                Bs[r][c * 4 + 0] = vb.x; Bs[r][c * 4 + 1] = vb.y;
                Bs[r][c * 4 + 2] = vb.z; Bs[r][c * 4 + 3] = vb.w;
            }
            __syncthreads();
#pragma unroll 8
            for (int d = 0; d < 64; d++) {
                float a0 = As[ty4 + 0][d], a1 = As[ty4 + 1][d];
                float a2 = As[ty4 + 2][d], a3 = As[ty4 + 3][d];
                float b0 = Bs[tx4 + 0][d], b1 = Bs[tx4 + 1][d];
                float b2 = Bs[tx4 + 2][d], b3 = Bs[tx4 + 3][d];
                acc[0][0] += a0 * b0; acc[0][1] += a0 * b1; acc[0][2] += a0 * b2; acc[0][3] += a0 * b3;
                acc[1][0] += a1 * b0; acc[1][1] += a1 * b1; acc[1][2] += a1 * b2; acc[1][3] += a1 * b3;
                acc[2][0] += a2 * b0; acc[2][1] += a2 * b1; acc[2][2] += a2 * b2; acc[2][3] += a2 * b3;
                acc[3][0] += a3 * b0; acc[3][1] += a3 * b1; acc[3][2] += a3 * b2; acc[3][3] += a3 * b3;
            }
            __syncthreads();
        }
        // epilogue for this 64-code chunk: distances + running argmin.
        // Mimic reference rounding: RN( RN(xnorm + enorm) - 2*dot ).
#pragma unroll
        for (int j = 0; j < 4; j++) {
            int k = kc * 64 + tx4 + j;
            float ec = g_enorm[k];
#pragma unroll
            for (int i = 0; i < 4; i++) {
                float s2 = xn[i] + ec;
                float dist = s2 - 2.0f * acc[i][j];
                if (dist < best[i]) { best[i] = dist; bidx[i] = k; }
            }
        }
    }

    // reduce argmin across the 16 tx threads that share each row
#pragma unroll
    for (int i = 0; i < 4; i++) {
        rv[ty4 + i][tx] = best[i];
        ri[ty4 + i][tx] = bidx[i];
    }
    __syncthreads();
    if (tid < 64) {
        float bv = rv[tid][0];
        int bi = ri[tid][0];
#pragma unroll
        for (int t = 1; t < 16; t++) {
            float v = rv[tid][t];
            int ii = ri[tid][t];
            if (v < bv || (v == bv && ii < bi)) { bv = v; bi = ii; }
        }
        int n = rowbase + tid;
        g_idx[n] = bi;
        atomicAdd(&g_counts[bi], 1);
        if (out_idx) out_idx[n] = (float)bi;
    }
}

// ---------------------------------------------------------------------------
// single block, 1024 threads: new_cluster_size, n_total, exclusive scan of counts
__global__ void k_scan(const float* __restrict__ ema_cs, float* __restrict__ out_ncs) {
    __shared__ int   sc[KK];
    __shared__ float red[KK];
    int t = threadIdx.x;
    int c = g_counts[t];
    float ncs = DECAYV * ema_cs[t] + (1.0f - DECAYV) * (float)c;
    g_ncs[t] = ncs;
    if (out_ncs) out_ncs[t] = ncs;

    red[t] = ncs;
    __syncthreads();
#pragma unroll
    for (int o = 512; o; o >>= 1) {
        if (t < o) red[t] += red[t + o];
        __syncthreads();
    }
    if (t == 0) g_ntotal = red[0] + EPSV;

    sc[t] = c;
    __syncthreads();
    for (int o = 1; o < KK; o <<= 1) {
        int u = (t >= o) ? sc[t - o] : 0;
        __syncthreads();
        sc[t] += u;
        __syncthreads();
    }
    g_offsets[t] = sc[t] - c;  // exclusive
}

__global__ __launch_bounds__(256) void k_scatter() {
    int n = blockIdx.x * 256 + threadIdx.x;
    int k = g_idx[n];
    int pos = atomicAdd(&g_cursor[k], 1);
    g_bucket[g_offsets[k] + pos] = n;
}

// one block per code: segment-sum of assigned rows + EMA update + new embedding
__global__ __launch_bounds__(256) void k_codesum(const float* __restrict__ flat,
                                                 const float* __restrict__ ema_avg,
                                                 float* __restrict__ out_ne,
                                                 float* __restrict__ out_nea) {
    __shared__ int sn[256];
    int k = blockIdx.x;
    int d = threadIdx.x;
    int start = g_offsets[k];
    int cnt = g_counts[k];
    float s = 0.f;
    for (int base = 0; base < cnt; base += 256) {
        int m = min(256, cnt - base);
        __syncthreads();
        if (d < m) sn[d] = g_bucket[start + base + d];
        __syncthreads();
        int t = 0;
        for (; t + 4 <= m; t += 4) {
            float v0 = flat[(size_t)sn[t + 0] * DD + d];
            float v1 = flat[(size_t)sn[t + 1] * DD + d];
            float v2 = flat[(size_t)sn[t + 2] * DD + d];
            float v3 = flat[(size_t)sn[t + 3] * DD + d];
            s += ((v0 + v1) + (v2 + v3));
        }
        for (; t < m; t++) s += flat[(size_t)sn[t] * DD + d];
    }
    float navg = DECAYV * ema_avg[(size_t)k * DD + d] + (1.0f - DECAYV) * s;
    if (out_nea) out_nea[(size_t)k * DD + d] = navg;
    float cs = (g_ncs[k] + EPSV) / g_ntotal;
    if (out_ne) out_ne[(size_t)k * DD + d] = navg / cs;
}

// ---------------------------------------------------------------------------
// quantized gather + straight-through rounding + MSE partial sums
__global__ __launch_bounds__(256) void k_quant(const float* __restrict__ flat,
                                               const float* __restrict__ emb,
                                               float* __restrict__ out_q) {
    int tid = threadIdx.x;
    int c = tid & 63;
    int rs = tid >> 6;
    int base = blockIdx.x * 64;
    const float4* f4 = (const float4*)flat;
    const float4* e4 = (const float4*)emb;
    float4* o4 = (float4*)out_q;
    float acc = 0.f;
#pragma unroll 4
    for (int it = 0; it < 16; it++) {
        int n = base + it * 4 + rs;
        int k = g_idx[n];
        float4 x = f4[(size_t)n * 64 + c];
        float4 e = e4[(size_t)k * 64 + c];
        float dx = e.x - x.x, dy = e.y - x.y, dz = e.z - x.z, dw = e.w - x.w;
        acc += dx * dx + dy * dy + dz * dz + dw * dw;
        if (out_q) {
            float4 st;
            st.x = x.x + dx; st.y = x.y + dy; st.z = x.z + dz; st.w = x.w + dw;
            o4[(size_t)n * 64 + c] = st;
        }
    }
    __shared__ float red[256];
    red[tid] = acc;
    __syncthreads();
#pragma unroll
    for (int o = 128; o; o >>= 1) {
        if (tid < o) red[tid] += red[tid + o];
        __syncthreads();
    }
    if (tid == 0) atomicAdd(&g_mse, red[0]);
}

// ---------------------------------------------------------------------------
// ortho loss: sum over i!=j of (e_i . e_j)^2 ; 32x32 tile per block
__global__ __launch_bounds__(256) void k_ortho(const float* __restrict__ emb) {
    __shared__ float Ei[32][65];
    __shared__ float Ej[32][65];
    int bi = blockIdx.x >> 5;
    int bj = blockIdx.x & 31;
    int tid = threadIdx.x;
    int tx = tid & 15, ty = tid >> 4;
    const float4* e4 = (const float4*)emb;
    float acc[2][2] = {{0.f, 0.f}, {0.f, 0.f}};
    for (int dc = 0; dc < 4; dc++) {
#pragma unroll
        for (int s = 0; s < 2; s++) {
            int i = s * 256 + tid;
            int r = i >> 4, c = i & 15;
            float4 va = e4[(size_t)(bi * 32 + r) * 64 + dc * 16 + c];
            Ei[r][c * 4 + 0] = va.x; Ei[r][c * 4 + 1] = va.y;
            Ei[r][c * 4 + 2] = va.z; Ei[r][c * 4 + 3] = va.w;
            float4 vb = e4[(size_t)(bj * 32 + r) * 64 + dc * 16 + c];
            Ej[r][c * 4 + 0] = vb.x; Ej[r][c * 4 + 1] = vb.y;
            Ej[r][c * 4 + 2] = vb.z; Ej[r][c * 4 + 3] = vb.w;
        }
        __syncthreads();
#pragma unroll 8
        for (int d = 0; d < 64; d++) {
            float a0 = Ei[ty * 2 + 0][d], a1 = Ei[ty * 2 + 1][d];
            float b0 = Ej[tx * 2 + 0][d], b1 = Ej[tx * 2 + 1][d];
            acc[0][0] += a0 * b0; acc[0][1] += a0 * b1;
            acc[1][0] += a1 * b0; acc[1][1] += a1 * b1;
        }
        __syncthreads();
    }
    float s = 0.f;
#pragma unroll
    for (int ii = 0; ii < 2; ii++)
#pragma unroll
        for (int jj = 0; jj < 2; jj++) {
            int gi = bi * 32 + ty * 2 + ii;
            int gj = bj * 32 + tx * 2 + jj;
            if (gi != gj) s += acc[ii][jj] * acc[ii][jj];
        }
    __shared__ float red[256];
    red[tid] = s;
    __syncthreads();
#pragma unroll
    for (int o = 128; o; o >>= 1) {
        if (tid < o) red[tid] += red[tid + o];
        __syncthreads();
    }
    if (tid == 0) atomicAdd(&g_ortho, red[0]);
}

__global__ void k_loss(float* __restrict__ out_loss) {
    float mse_mean = g_mse / 33554432.0f;
    float loss = mse_mean + 0.25f * mse_mean + 0.09f * sqrtf(g_ortho);
    if (out_loss) *out_loss = loss;
}

// ---------------------------------------------------------------------------
extern "C" void kernel_launch(void* const* d_in, const int* in_sizes, int n_in,
                              void* d_out, int out_size) {
    const float* flat    = (const float*)d_in[0];
    const float* emb     = (const float*)d_in[1];
    const float* ema_cs  = (const float*)d_in[2];
    const float* ema_avg = (const float*)d_in[3];
    float* out = (float*)d_out;

    // full concatenated layout: quantized_st | loss | indices | new_embedding
    //                           | new_cluster_size | new_embedding_avg
    const int FULL = 34210817;
    bool isfull = (out_size >= FULL);
    float* out_q    = out;
    float* out_loss = isfull ? out + 33554432 : nullptr;
    float* out_idx  = isfull ? out + 33554433 : nullptr;
    float* out_ne   = isfull ? out + 33685505 : nullptr;
    float* out_ncs  = isfull ? out + 33947649 : nullptr;
    float* out_nea  = isfull ? out + 33948673 : nullptr;

    k_init<<<4, 256>>>();
    k_norms<<<(NN + KK) / 8, 256>>>(flat, emb);
    k_argmin<<<NN / 64, 256>>>(flat, emb, out_idx);
    k_scan<<<1, 1024>>>(ema_cs, out_ncs);
    k_scatter<<<NN / 256, 256>>>();
    k_codesum<<<KK, 256>>>(flat, ema_avg, out_ne, out_nea);
    k_quant<<<NN / 64, 256>>>(flat, emb, out_q);
    k_ortho<<<1024, 256>>>(emb);
    k_loss<<<1, 1>>>(out_loss);
}

// round 8
// speedup vs baseline: 1.5298x; 1.5298x over previous
#include <cuda_runtime.h>
#include <cuda_bf16.h>
#include <math.h>
#include <stdint.h>

#define NN 131072
#define DD 256
#define KK 1024
#define EPSV 1e-5f
#define DECAYV 0.99f
#define GAP_EPS 1e-4f

// ---- scratch (no allocations allowed) ----
__device__ float g_xnorm[NN];
__device__ float g_enorm[KK];
__device__ int   g_idx[NN];
__device__ int   g_counts[KK];
__device__ int   g_offsets[KK];
__device__ int   g_cursor[KK];
__device__ int   g_bucket[NN];
__device__ float g_ncs[KK];
__device__ float g_ntotal;
__device__ float g_mse;
__device__ float g_ortho;
// embedding bf16 2-splits (hi/lo)
__device__ __align__(16) __nv_bfloat16 g_eh[KK * DD];
__device__ __align__(16) __nv_bfloat16 g_el[KK * DD];

// ======================= PTX helpers (all compute_103-safe) =======================
__device__ __forceinline__ uint32_t smem_to_u32(const void* p) {
    uint32_t a;
    asm("{ .reg .u64 t; cvta.to.shared.u64 t, %1; cvt.u32.u64 %0, t; }" : "=r"(a) : "l"(p));
    return a;
}
#define LDSM_X4(r0, r1, r2, r3, addr) \
    asm volatile("ldmatrix.sync.aligned.m8n8.x4.shared.b16 {%0,%1,%2,%3}, [%4];" \
                 : "=r"(r0), "=r"(r1), "=r"(r2), "=r"(r3) : "r"(addr))
#define MMA16816(c, a0, a1, a2, a3, b0, b1) \
    asm volatile("mma.sync.aligned.m16n8k16.row.col.f32.bf16.bf16.f32 " \
                 "{%0,%1,%2,%3},{%4,%5,%6,%7},{%8,%9},{%0,%1,%2,%3};" \
                 : "+f"((c)[0]), "+f"((c)[1]), "+f"((c)[2]), "+f"((c)[3]) \
                 : "r"(a0), "r"(a1), "r"(a2), "r"(a3), "r"(b0), "r"(b1))
#define CPA16(dst, src) \
    asm volatile("cp.async.cg.shared.global [%0], [%1], 16;" :: "r"(dst), "l"(src))
#define CPA_COMMIT() asm volatile("cp.async.commit_group;" ::: "memory")

// top-2 update with lowest-index tie-break (reference argmin semantics)
#define UPD2(d, k, b1, i1, b2, i2) do { \
    float _d = (d); int _k = (k); \
    if (_d < (b1) || (_d == (b1) && _k < (i1))) { (b2) = (b1); (i2) = (i1); (b1) = _d; (i1) = _k; } \
    else if (_d < (b2) || (_d == (b2) && _k < (i2))) { (b2) = _d; (i2) = _k; } } while (0)

// ======================= smem layout for mma kernel =======================
// A_h[128][264 bf16] (row stride 528B), A_l same, B double-buffer [128][40 bf16] (80B)
#define SA_H   0
#define SA_L   67584
#define SB_B   135168
#define SB_SZ  10240
#define S_EN   155648
#define S_B1   156160
#define S_I1   158208
#define S_B2   160256
#define S_I2   162304
#define SMEM_TOTAL 164352

// ======================= small kernels =======================
__global__ void k_init() {
    int t = blockIdx.x * blockDim.x + threadIdx.x;
    if (t < KK) { g_counts[t] = 0; g_cursor[t] = 0; }
    if (t == 0) { g_mse = 0.f; g_ortho = 0.f; }
}

__device__ __forceinline__ void split2(float x, unsigned short& h, unsigned short& l) {
    __nv_bfloat16 bh = __float2bfloat16(x);
    float r1 = x - __bfloat162float(bh);
    __nv_bfloat16 bl = __float2bfloat16(r1);
    h = __bfloat16_as_ushort(bh); l = __bfloat16_as_ushort(bl);
}

__global__ __launch_bounds__(256) void k_embsplit(const float* __restrict__ emb) {
    int i = blockIdx.x * 256 + threadIdx.x;  // over KK*DD/4
    const float4* e4 = (const float4*)emb;
    float4 v = e4[i];
    float x[4] = {v.x, v.y, v.z, v.w};
    unsigned short h[4], l[4];
#pragma unroll
    for (int j = 0; j < 4; j++) split2(x[j], h[j], l[j]);
    uint2 uh, ul;
    uh.x = (uint32_t)h[0] | ((uint32_t)h[1] << 16); uh.y = (uint32_t)h[2] | ((uint32_t)h[3] << 16);
    ul.x = (uint32_t)l[0] | ((uint32_t)l[1] << 16); ul.y = (uint32_t)l[2] | ((uint32_t)l[3] << 16);
    ((uint2*)g_eh)[i] = uh; ((uint2*)g_el)[i] = ul;
}

__global__ __launch_bounds__(256) void k_norms(const float* __restrict__ flat,
                                               const float* __restrict__ emb) {
    int warp = (blockIdx.x * blockDim.x + threadIdx.x) >> 5;
    int lane = threadIdx.x & 31;
    if (warp >= NN + KK) return;
    const float4* p4 = (warp < NN)
        ? (const float4*)(flat + (size_t)warp * DD)
        : (const float4*)(emb + (size_t)(warp - NN) * DD);
    float s = 0.f;
#pragma unroll
    for (int c = 0; c < 2; c++) {
        float4 v = p4[lane + 32 * c];
        s += v.x * v.x + v.y * v.y + v.z * v.z + v.w * v.w;
    }
#pragma unroll
    for (int o = 16; o; o >>= 1) s += __shfl_xor_sync(0xffffffffu, s, o);
    if (lane == 0) {
        if (warp < NN) g_xnorm[warp] = s;
        else           g_enorm[warp - NN] = s;
    }
}

// exact fp32 rescore of one (row, code) distance — reference-style rounding
__device__ __forceinline__ float exact_dist(const float4* __restrict__ f4,
                                            const float4* __restrict__ e4,
                                            int n, int k, float xn) {
    float s0 = 0.f, s1 = 0.f, s2 = 0.f, s3 = 0.f;
#pragma unroll 8
    for (int c = 0; c < 64; c++) {
        float4 x = f4[(size_t)n * 64 + c];
        float4 e = e4[(size_t)k * 64 + c];
        s0 += x.x * e.x; s1 += x.y * e.y; s2 += x.z * e.z; s3 += x.w * e.w;
    }
    float dot = (s0 + s1) + (s2 + s3);
    return (xn + g_enorm[k]) - 2.0f * dot;
}

// ======================= bf16 HMMA argmin =======================
// CTA: 256 threads = 8 warps (wm in {0,1} over 64 rows, wn in {0..3} over 32 cols).
// Per CTA: 128 rows x 1024 codes, dot via 3-term 2-split bf16 mma (hh + lh + hl).
// Top-2 tracked per row; near-ties (gap <= GAP_EPS) rescored exactly in fp32.
__global__ __launch_bounds__(256, 1) void k_argmin_mma(const float* __restrict__ flat,
                                                       const float* __restrict__ emb,
                                                       float* __restrict__ out_idx) {
    extern __shared__ __align__(16) char smem[];
    uint32_t sb = smem_to_u32(smem);
    int tid = threadIdx.x;
    int lane = tid & 31, wid = tid >> 5;
    int wm = wid >> 2, wn = wid & 3;
    int rowbase = blockIdx.x * 128;

    // ---- phase 0: load A fp32, split to bf16 hi/lo into persistent smem ----
    const float4* f4 = (const float4*)flat;
#pragma unroll
    for (int it = 0; it < 32; it++) {
        int idx = it * 256 + tid;
        int r = idx >> 6, c4 = idx & 63;
        float4 v = f4[((size_t)(rowbase + r)) * 64 + c4];
        float x[4] = {v.x, v.y, v.z, v.w};
        unsigned short h[4], l[4];
#pragma unroll
        for (int j = 0; j < 4; j++) split2(x[j], h[j], l[j]);
        uint2 uh, ul;
        uh.x = (uint32_t)h[0] | ((uint32_t)h[1] << 16); uh.y = (uint32_t)h[2] | ((uint32_t)h[3] << 16);
        ul.x = (uint32_t)l[0] | ((uint32_t)l[1] << 16); ul.y = (uint32_t)l[2] | ((uint32_t)l[3] << 16);
        *(uint2*)(smem + SA_H + r * 528 + c4 * 8) = uh;
        *(uint2*)(smem + SA_L + r * 528 + c4 * 8) = ul;
    }

    // per-thread row norms for the 8 rows this thread's C fragments cover
    float xn8[8];
#pragma unroll
    for (int i = 0; i < 4; i++)
#pragma unroll
        for (int j = 0; j < 2; j++)
            xn8[i * 2 + j] = g_xnorm[rowbase + wm * 64 + i * 16 + j * 8 + (lane >> 2)];

    float b1v[8], b2v[8];
    int b1i[8], b2i[8];
#pragma unroll
    for (int i = 0; i < 8; i++) { b1v[i] = 3.4e38f; b2v[i] = 3.4e38f; b1i[i] = 0; b2i[i] = 0; }

    // lane-derived ldmatrix addressing
    int a_row = lane & 15;
    int a_kof = (lane >> 4) * 8;
    int b_nof = (lane & 7) + ((lane >> 4) & 1) * 8;
    int b_kof = ((lane >> 3) & 1) * 8;
    float* s_en = (float*)(smem + S_EN);

    for (int nt = 0; nt < 8; nt++) {
        if (tid < 128) s_en[tid] = g_enorm[nt * 128 + tid];
        float acc[4][4][4];
#pragma unroll
        for (int i = 0; i < 4; i++)
#pragma unroll
            for (int nf = 0; nf < 4; nf++)
#pragma unroll
                for (int c = 0; c < 4; c++) acc[i][nf][c] = 0.f;

        // prefetch chunk 0 (chunks 0..7: B_h, 8..15: B_l; each 128 codes x 32 dims)
        {
            const __nv_bfloat16* src = g_eh;
            int r = tid >> 1, half = tid & 1;
            const char* gs = (const char*)(src + ((size_t)(nt * 128 + r)) * 256) + half * 32;
            uint32_t ds = sb + SB_B + r * 80 + half * 32;
            CPA16(ds, gs); CPA16(ds + 16, gs + 16);
            CPA_COMMIT();
        }

        for (int ci = 0; ci < 16; ci++) {
            if (ci < 15) {
                int cn = ci + 1;
                const __nv_bfloat16* src = (cn < 8) ? g_eh : g_el;
                int kb32 = (cn & 7) * 32;
                int r = tid >> 1, half = tid & 1;
                const char* gs = (const char*)(src + ((size_t)(nt * 128 + r)) * 256 + kb32) + half * 32;
                uint32_t ds = sb + SB_B + (cn & 1) * SB_SZ + r * 80 + half * 32;
                CPA16(ds, gs); CPA16(ds + 16, gs + 16);
                CPA_COMMIT();
                asm volatile("cp.async.wait_group 1;" ::: "memory");
            } else {
                asm volatile("cp.async.wait_group 0;" ::: "memory");
            }
            __syncthreads();

            int kb = (ci & 7) * 32;
            uint32_t bbase = sb + SB_B + (ci & 1) * SB_SZ;
            int nterms = (ci < 8) ? 2 : 1;
            for (int term = 0; term < nterms; term++) {
                uint32_t abase = sb + (term ? SA_L : SA_H);
#pragma unroll
                for (int kk = 0; kk < 2; kk++) {
                    uint32_t a[4][4];
#pragma unroll
                    for (int i = 0; i < 4; i++) {
                        uint32_t ad = abase + (uint32_t)(wm * 64 + i * 16 + a_row) * 528u
                                    + (uint32_t)(kb + kk * 16 + a_kof) * 2u;
                        LDSM_X4(a[i][0], a[i][1], a[i][2], a[i][3], ad);
                    }
                    uint32_t b[2][4];
#pragma unroll
                    for (int p = 0; p < 2; p++) {
                        uint32_t bd = bbase + (uint32_t)(wn * 32 + p * 16 + b_nof) * 80u
                                    + (uint32_t)(kk * 16 + b_kof) * 2u;
                        LDSM_X4(b[p][0], b[p][1], b[p][2], b[p][3], bd);
                    }
#pragma unroll
                    for (int i = 0; i < 4; i++) {
                        MMA16816(acc[i][0], a[i][0], a[i][1], a[i][2], a[i][3], b[0][0], b[0][1]);
                        MMA16816(acc[i][1], a[i][0], a[i][1], a[i][2], a[i][3], b[0][2], b[0][3]);
                        MMA16816(acc[i][2], a[i][0], a[i][1], a[i][2], a[i][3], b[1][0], b[1][1]);
                        MMA16816(acc[i][3], a[i][0], a[i][1], a[i][2], a[i][3], b[1][2], b[1][3]);
                    }
                }
            }
            __syncthreads();
        }

        // ---- epilogue: distances + running top-2 (reference rounding kept) ----
#pragma unroll
        for (int i = 0; i < 4; i++)
#pragma unroll
            for (int nf = 0; nf < 4; nf++) {
                int cb = wn * 32 + nf * 8 + (lane & 3) * 2;
                float en0 = s_en[cb], en1 = s_en[cb + 1];
                int k0 = nt * 128 + cb;
                int s0 = i * 2, s1 = i * 2 + 1;
                float d;
                d = (xn8[s0] + en0) - 2.0f * acc[i][nf][0];
                UPD2(d, k0,     b1v[s0], b1i[s0], b2v[s0], b2i[s0]);
                d = (xn8[s0] + en1) - 2.0f * acc[i][nf][1];
                UPD2(d, k0 + 1, b1v[s0], b1i[s0], b2v[s0], b2i[s0]);
                d = (xn8[s1] + en0) - 2.0f * acc[i][nf][2];
                UPD2(d, k0,     b1v[s1], b1i[s1], b2v[s1], b2i[s1]);
                d = (xn8[s1] + en1) - 2.0f * acc[i][nf][3];
                UPD2(d, k0 + 1, b1v[s1], b1i[s1], b2v[s1], b2i[s1]);
            }
        __syncthreads();  // protect s_en before next nt overwrites it
    }

    // ---- cross-lane merge (4 lanes share a row): merge top-2 sets ----
#pragma unroll
    for (int off = 1; off <= 2; off <<= 1)
#pragma unroll
        for (int idx = 0; idx < 8; idx++) {
            float o1v = __shfl_xor_sync(0xffffffffu, b1v[idx], off);
            int   o1i = __shfl_xor_sync(0xffffffffu, b1i[idx], off);
            float o2v = __shfl_xor_sync(0xffffffffu, b2v[idx], off);
            int   o2i = __shfl_xor_sync(0xffffffffu, b2i[idx], off);
            UPD2(o1v, o1i, b1v[idx], b1i[idx], b2v[idx], b2i[idx]);
            UPD2(o2v, o2i, b1v[idx], b1i[idx], b2v[idx], b2i[idx]);
        }
    float* sv1 = (float*)(smem + S_B1);
    int*   si1 = (int*)(smem + S_I1);
    float* sv2 = (float*)(smem + S_B2);
    int*   si2 = (int*)(smem + S_I2);
    if ((lane & 3) == 0) {
#pragma unroll
        for (int idx = 0; idx < 8; idx++) {
            int i = idx >> 1, j = idx & 1;
            int row = wm * 64 + i * 16 + j * 8 + (lane >> 2);
            sv1[row * 4 + wn] = b1v[idx]; si1[row * 4 + wn] = b1i[idx];
            sv2[row * 4 + wn] = b2v[idx]; si2[row * 4 + wn] = b2i[idx];
        }
    }
    __syncthreads();
    if (tid < 128) {
        float bv = sv1[tid * 4], b2 = sv2[tid * 4];
        int bk = si1[tid * 4], k2 = si2[tid * 4];
#pragma unroll
        for (int w = 1; w < 4; w++) {
            float o1 = sv1[tid * 4 + w], o2 = sv2[tid * 4 + w];
            int p1 = si1[tid * 4 + w], p2 = si2[tid * 4 + w];
            UPD2(o1, p1, bv, bk, b2, k2);
            UPD2(o2, p2, bv, bk, b2, k2);
        }
        int n = rowbase + tid;
        // near-tie: exact fp32 rescore of the two candidates (reference semantics)
        if (b2 - bv <= GAP_EPS) {
            float xn = g_xnorm[n];
            float d1 = exact_dist(f4, (const float4*)emb, n, bk, xn);
            float d2 = exact_dist(f4, (const float4*)emb, n, k2, xn);
            if (d2 < d1 || (d2 == d1 && k2 < bk)) bk = k2;
        }
        g_idx[n] = bk;
        atomicAdd(&g_counts[bk], 1);
        if (out_idx) out_idx[n] = (float)bk;
    }
}

// ======================= EMA / losses (as R2) =======================
__global__ void k_scan(const float* __restrict__ ema_cs, float* __restrict__ out_ncs) {
    __shared__ int   sc[KK];
    __shared__ float red[KK];
    int t = threadIdx.x;
    int c = g_counts[t];
    float ncs = DECAYV * ema_cs[t] + (1.0f - DECAYV) * (float)c;
    g_ncs[t] = ncs;
    if (out_ncs) out_ncs[t] = ncs;
    red[t] = ncs;
    __syncthreads();
#pragma unroll
    for (int o = 512; o; o >>= 1) {
        if (t < o) red[t] += red[t + o];
        __syncthreads();
    }
    if (t == 0) g_ntotal = red[0] + EPSV;
    sc[t] = c;
    __syncthreads();
    for (int o = 1; o < KK; o <<= 1) {
        int u = (t >= o) ? sc[t - o] : 0;
        __syncthreads();
        sc[t] += u;
        __syncthreads();
    }
    g_offsets[t] = sc[t] - c;
}

__global__ __launch_bounds__(256) void k_scatter() {
    int n = blockIdx.x * 256 + threadIdx.x;
    int k = g_idx[n];
    int pos = atomicAdd(&g_cursor[k], 1);
    g_bucket[g_offsets[k] + pos] = n;
}

__global__ __launch_bounds__(256) void k_codesum(const float* __restrict__ flat,
                                                 const float* __restrict__ ema_avg,
                                                 float* __restrict__ out_ne,
                                                 float* __restrict__ out_nea) {
    __shared__ int sn[256];
    int k = blockIdx.x;
    int d = threadIdx.x;
    int start = g_offsets[k];
    int cnt = g_counts[k];
    float s = 0.f;
    for (int base = 0; base < cnt; base += 256) {
        int m = min(256, cnt - base);
        __syncthreads();
        if (d < m) sn[d] = g_bucket[start + base + d];
        __syncthreads();
        int t = 0;
        for (; t + 4 <= m; t += 4) {
            float v0 = flat[(size_t)sn[t + 0] * DD + d];
            float v1 = flat[(size_t)sn[t + 1] * DD + d];
            float v2 = flat[(size_t)sn[t + 2] * DD + d];
            float v3 = flat[(size_t)sn[t + 3] * DD + d];
            s += ((v0 + v1) + (v2 + v3));
        }
        for (; t < m; t++) s += flat[(size_t)sn[t] * DD + d];
    }
    float navg = DECAYV * ema_avg[(size_t)k * DD + d] + (1.0f - DECAYV) * s;
    if (out_nea) out_nea[(size_t)k * DD + d] = navg;
    float cs = (g_ncs[k] + EPSV) / g_ntotal;
    if (out_ne) out_ne[(size_t)k * DD + d] = navg / cs;
}

__global__ __launch_bounds__(256) void k_quant(const float* __restrict__ flat,
                                               const float* __restrict__ emb,
                                               float* __restrict__ out_q) {
    int tid = threadIdx.x;
    int c = tid & 63;
    int rs = tid >> 6;
    int base = blockIdx.x * 64;
    const float4* f4 = (const float4*)flat;
    const float4* e4 = (const float4*)emb;
    float4* o4 = (float4*)out_q;
    float acc = 0.f;
#pragma unroll 4
    for (int it = 0; it < 16; it++) {
        int n = base + it * 4 + rs;
        int k = g_idx[n];
        float4 x = f4[(size_t)n * 64 + c];
        float4 e = e4[(size_t)k * 64 + c];
        float dx = e.x - x.x, dy = e.y - x.y, dz = e.z - x.z, dw = e.w - x.w;
        acc += dx * dx + dy * dy + dz * dz + dw * dw;
        if (out_q) {
            float4 st;
            st.x = x.x + dx; st.y = x.y + dy; st.z = x.z + dz; st.w = x.w + dw;
            o4[(size_t)n * 64 + c] = st;
        }
    }
    __shared__ float red[256];
    red[tid] = acc;
    __syncthreads();
#pragma unroll
    for (int o = 128; o; o >>= 1) {
        if (tid < o) red[tid] += red[tid + o];
        __syncthreads();
    }
    if (tid == 0) atomicAdd(&g_mse, red[0]);
}

__global__ __launch_bounds__(256) void k_ortho(const float* __restrict__ emb) {
    __shared__ float Ei[32][65];
    __shared__ float Ej[32][65];
    int bi = blockIdx.x >> 5;
    int bj = blockIdx.x & 31;
    int tid = threadIdx.x;
    int tx = tid & 15, ty = tid >> 4;
    const float4* e4 = (const float4*)emb;
    float acc[2][2] = {{0.f, 0.f}, {0.f, 0.f}};
    for (int dc = 0; dc < 4; dc++) {
#pragma unroll
        for (int s = 0; s < 2; s++) {
            int i = s * 256 + tid;
            int r = i >> 4, c = i & 15;
            float4 va = e4[(size_t)(bi * 32 + r) * 64 + dc * 16 + c];
            Ei[r][c * 4 + 0] = va.x; Ei[r][c * 4 + 1] = va.y;
            Ei[r][c * 4 + 2] = va.z; Ei[r][c * 4 + 3] = va.w;
            float4 vb = e4[(size_t)(bj * 32 + r) * 64 + dc * 16 + c];
            Ej[r][c * 4 + 0] = vb.x; Ej[r][c * 4 + 1] = vb.y;
            Ej[r][c * 4 + 2] = vb.z; Ej[r][c * 4 + 3] = vb.w;
        }
        __syncthreads();
#pragma unroll 8
        for (int d = 0; d < 64; d++) {
            float a0 = Ei[ty * 2 + 0][d], a1 = Ei[ty * 2 + 1][d];
            float b0 = Ej[tx * 2 + 0][d], b1 = Ej[tx * 2 + 1][d];
            acc[0][0] += a0 * b0; acc[0][1] += a0 * b1;
            acc[1][0] += a1 * b0; acc[1][1] += a1 * b1;
        }
        __syncthreads();
    }
    float s = 0.f;
#pragma unroll
    for (int ii = 0; ii < 2; ii++)
#pragma unroll
        for (int jj = 0; jj < 2; jj++) {
            int gi = bi * 32 + ty * 2 + ii;
            int gj = bj * 32 + tx * 2 + jj;
            if (gi != gj) s += acc[ii][jj] * acc[ii][jj];
        }
    __shared__ float red[256];
    red[tid] = s;
    __syncthreads();
#pragma unroll
    for (int o = 128; o; o >>= 1) {
        if (tid < o) red[tid] += red[tid + o];
        __syncthreads();
    }
    if (tid == 0) atomicAdd(&g_ortho, red[0]);
}

__global__ void k_loss(float* __restrict__ out_loss) {
    float mse_mean = g_mse / 33554432.0f;
    float loss = mse_mean + 0.25f * mse_mean + 0.09f * sqrtf(g_ortho);
    if (out_loss) *out_loss = loss;
}

// ---------------------------------------------------------------------------
extern "C" void kernel_launch(void* const* d_in, const int* in_sizes, int n_in,
                              void* d_out, int out_size) {
    const float* flat    = (const float*)d_in[0];
    const float* emb     = (const float*)d_in[1];
    const float* ema_cs  = (const float*)d_in[2];
    const float* ema_avg = (const float*)d_in[3];
    float* out = (float*)d_out;

    const int FULL = 34210817;
    bool isfull = (out_size >= FULL);
    float* out_q    = out;
    float* out_loss = isfull ? out + 33554432 : nullptr;
    float* out_idx  = isfull ? out + 33554433 : nullptr;
    float* out_ne   = isfull ? out + 33685505 : nullptr;
    float* out_ncs  = isfull ? out + 33947649 : nullptr;
    float* out_nea  = isfull ? out + 33948673 : nullptr;

    cudaFuncSetAttribute(k_argmin_mma, cudaFuncAttributeMaxDynamicSharedMemorySize, SMEM_TOTAL);

    k_init<<<4, 256>>>();
    k_embsplit<<<KK * DD / 4 / 256, 256>>>(emb);
    k_norms<<<(NN + KK) / 8, 256>>>(flat, emb);
    k_argmin_mma<<<NN / 128, 256, SMEM_TOTAL>>>(flat, emb, out_idx);
    k_scan<<<1, 1024>>>(ema_cs, out_ncs);
    k_scatter<<<NN / 256, 256>>>();
    k_codesum<<<KK, 256>>>(flat, ema_avg, out_ne, out_nea);
    k_quant<<<NN / 64, 256>>>(flat, emb, out_q);
    k_ortho<<<1024, 256>>>(emb);
    k_loss<<<1, 1>>>(out_loss);
}

// round 9
// speedup vs baseline: 3.0780x; 2.0121x over previous
#include <cuda_runtime.h>
#include <cuda_bf16.h>
#include <math.h>
#include <stdint.h>

#define NN 131072
#define DD 256
#define KK 1024
#define EPSV 1e-5f
#define DECAYV 0.99f
#define GAP_EPS 1e-4f

// ---- scratch (no allocations allowed) ----
__device__ float g_xnorm[NN];
__device__ float g_enorm[KK];
__device__ int   g_idx[NN];
__device__ int   g_counts[KK];
__device__ int   g_offsets[KK];
__device__ int   g_cursor[KK];
__device__ int   g_bucket[NN];
__device__ float g_ncs[KK];
__device__ float g_ntotal;
__device__ float g_mse;
__device__ float g_ortho;
// embedding bf16 2-splits (hi/lo)
__device__ __align__(16) __nv_bfloat16 g_eh[KK * DD];
__device__ __align__(16) __nv_bfloat16 g_el[KK * DD];

// ======================= PTX helpers (all compute_103-safe) =======================
__device__ __forceinline__ uint32_t smem_to_u32(const void* p) {
    uint32_t a;
    asm("{ .reg .u64 t; cvta.to.shared.u64 t, %1; cvt.u32.u64 %0, t; }" : "=r"(a) : "l"(p));
    return a;
}
#define LDSM_X4(r0, r1, r2, r3, addr) \
    asm volatile("ldmatrix.sync.aligned.m8n8.x4.shared.b16 {%0,%1,%2,%3}, [%4];" \
                 : "=r"(r0), "=r"(r1), "=r"(r2), "=r"(r3) : "r"(addr))
#define MMA16816(c, a0, a1, a2, a3, b0, b1) \
    asm volatile("mma.sync.aligned.m16n8k16.row.col.f32.bf16.bf16.f32 " \
                 "{%0,%1,%2,%3},{%4,%5,%6,%7},{%8,%9},{%0,%1,%2,%3};" \
                 : "+f"((c)[0]), "+f"((c)[1]), "+f"((c)[2]), "+f"((c)[3]) \
                 : "r"(a0), "r"(a1), "r"(a2), "r"(a3), "r"(b0), "r"(b1))
#define CPA16(dst, src) \
    asm volatile("cp.async.cg.shared.global [%0], [%1], 16;" :: "r"(dst), "l"(src))
#define CPA_COMMIT() asm volatile("cp.async.commit_group;" ::: "memory")

// top-2 update with lowest-index tie-break (reference argmin semantics)
#define UPD2(d, k, b1, i1, b2, i2) do { \
    float _d = (d); int _k = (k); \
    if (_d < (b1) || (_d == (b1) && _k < (i1))) { (b2) = (b1); (i2) = (i1); (b1) = _d; (i1) = _k; } \
    else if (_d < (b2) || (_d == (b2) && _k < (i2))) { (b2) = _d; (i2) = _k; } } while (0)

// ======================= smem layout for mma kernel =======================
// A_h[128][264 bf16] (stride 528B), A_l same; B ring: 3 bufs of 128x(64 bf16 + pad) (144B stride)
#define SA_H   0
#define SA_L   67584
#define SB_B   135168
#define SB_STR 144
#define SB_SZ  18432
#define S_EN   190464
#define S_B1   190976
#define S_I1   193024
#define S_B2   195072
#define S_I2   197120
#define SMEM_TOTAL 199168

// ======================= small kernels =======================
__global__ void k_init() {
    int t = blockIdx.x * blockDim.x + threadIdx.x;
    if (t < KK) { g_counts[t] = 0; g_cursor[t] = 0; }
    if (t == 0) { g_mse = 0.f; g_ortho = 0.f; }
}

__device__ __forceinline__ void split2(float x, unsigned short& h, unsigned short& l) {
    __nv_bfloat16 bh = __float2bfloat16(x);
    float r1 = x - __bfloat162float(bh);
    __nv_bfloat16 bl = __float2bfloat16(r1);
    h = __bfloat16_as_ushort(bh); l = __bfloat16_as_ushort(bl);
}

__global__ __launch_bounds__(256) void k_embsplit(const float* __restrict__ emb) {
    int i = blockIdx.x * 256 + threadIdx.x;  // over KK*DD/4
    const float4* e4 = (const float4*)emb;
    float4 v = e4[i];
    float x[4] = {v.x, v.y, v.z, v.w};
    unsigned short h[4], l[4];
#pragma unroll
    for (int j = 0; j < 4; j++) split2(x[j], h[j], l[j]);
    uint2 uh, ul;
    uh.x = (uint32_t)h[0] | ((uint32_t)h[1] << 16); uh.y = (uint32_t)h[2] | ((uint32_t)h[3] << 16);
    ul.x = (uint32_t)l[0] | ((uint32_t)l[1] << 16); ul.y = (uint32_t)l[2] | ((uint32_t)l[3] << 16);
    ((uint2*)g_eh)[i] = uh; ((uint2*)g_el)[i] = ul;
}

__global__ __launch_bounds__(256) void k_norms(const float* __restrict__ flat,
                                               const float* __restrict__ emb) {
    int warp = (blockIdx.x * blockDim.x + threadIdx.x) >> 5;
    int lane = threadIdx.x & 31;
    if (warp >= NN + KK) return;
    const float4* p4 = (warp < NN)
        ? (const float4*)(flat + (size_t)warp * DD)
        : (const float4*)(emb + (size_t)(warp - NN) * DD);
    float s = 0.f;
#pragma unroll
    for (int c = 0; c < 2; c++) {
        float4 v = p4[lane + 32 * c];
        s += v.x * v.x + v.y * v.y + v.z * v.z + v.w * v.w;
    }
#pragma unroll
    for (int o = 16; o; o >>= 1) s += __shfl_xor_sync(0xffffffffu, s, o);
    if (lane == 0) {
        if (warp < NN) g_xnorm[warp] = s;
        else           g_enorm[warp - NN] = s;
    }
}

// exact fp32 rescore of one (row, code) distance — reference-style rounding
__device__ __forceinline__ float exact_dist(const float4* __restrict__ f4,
                                            const float4* __restrict__ e4,
                                            int n, int k, float xn) {
    float s0 = 0.f, s1 = 0.f, s2 = 0.f, s3 = 0.f;
#pragma unroll 8
    for (int c = 0; c < 64; c++) {
        float4 x = f4[(size_t)n * 64 + c];
        float4 e = e4[(size_t)k * 64 + c];
        s0 += x.x * e.x; s1 += x.y * e.y; s2 += x.z * e.z; s3 += x.w * e.w;
    }
    float dot = (s0 + s1) + (s2 + s3);
    return (xn + g_enorm[k]) - 2.0f * dot;
}

// ======================= bf16 HMMA argmin =======================
// CTA: 512 threads = 16 warps (wm 0..3 over 32 rows each, wn 0..3 over 32 cols).
// Per CTA: 128 rows x 1024 codes; dot via 3-term 2-split bf16 mma (hh + lh + hl).
// B streamed in 128x64-dim chunks, triple-buffered cp.async, one barrier per chunk.
// Top-2 per row; near-ties (gap <= GAP_EPS) rescored exactly in fp32.
__global__ __launch_bounds__(512, 1) void k_argmin_mma(const float* __restrict__ flat,
                                                       const float* __restrict__ emb,
                                                       float* __restrict__ out_idx) {
    extern __shared__ __align__(16) char smem[];
    uint32_t sb = smem_to_u32(smem);
    int tid = threadIdx.x;
    int lane = tid & 31, wid = tid >> 5;
    int wm = wid >> 2, wn = wid & 3;
    int rowbase = blockIdx.x * 128;

    // ---- phase 0: load A fp32, split to bf16 hi/lo into persistent smem ----
    const float4* f4 = (const float4*)flat;
#pragma unroll
    for (int it = 0; it < 16; it++) {
        int idx = it * 512 + tid;
        int r = idx >> 6, c4 = idx & 63;
        float4 v = f4[((size_t)(rowbase + r)) * 64 + c4];
        float x[4] = {v.x, v.y, v.z, v.w};
        unsigned short h[4], l[4];
#pragma unroll
        for (int j = 0; j < 4; j++) split2(x[j], h[j], l[j]);
        uint2 uh, ul;
        uh.x = (uint32_t)h[0] | ((uint32_t)h[1] << 16); uh.y = (uint32_t)h[2] | ((uint32_t)h[3] << 16);
        ul.x = (uint32_t)l[0] | ((uint32_t)l[1] << 16); ul.y = (uint32_t)l[2] | ((uint32_t)l[3] << 16);
        *(uint2*)(smem + SA_H + r * 528 + c4 * 8) = uh;
        *(uint2*)(smem + SA_L + r * 528 + c4 * 8) = ul;
    }

    // per-thread row norms for the 4 row-slots this thread's C fragments cover
    float xn4[4];
#pragma unroll
    for (int i = 0; i < 2; i++)
#pragma unroll
        for (int j = 0; j < 2; j++)
            xn4[i * 2 + j] = g_xnorm[rowbase + wm * 32 + i * 16 + j * 8 + (lane >> 2)];

    float b1v[4], b2v[4];
    int b1i[4], b2i[4];
#pragma unroll
    for (int i = 0; i < 4; i++) { b1v[i] = 3.4e38f; b2v[i] = 3.4e38f; b1i[i] = 0; b2i[i] = 0; }

    // lane-derived ldmatrix addressing
    int a_row = lane & 15;
    int a_kof = (lane >> 4) * 8;
    int b_nof = (lane & 7) + ((lane >> 4) & 1) * 8;
    int b_kof = ((lane >> 3) & 1) * 8;
    float* s_en = (float*)(smem + S_EN);
    int pr = tid >> 2, pq = tid & 3;  // prefetch row / 32B quarter

    for (int nt = 0; nt < 8; nt++) {
        if (tid < 128) s_en[tid] = g_enorm[nt * 128 + tid];
        float acc[2][4][4];
#pragma unroll
        for (int i = 0; i < 2; i++)
#pragma unroll
            for (int nf = 0; nf < 4; nf++)
#pragma unroll
                for (int c = 0; c < 4; c++) acc[i][nf][c] = 0.f;

        // prefetch chunk 0 (chunks 0..3: B_h dims, 4..7: B_l dims; each 128 codes x 64 dims)
        {
            const char* gs = (const char*)(g_eh + ((size_t)(nt * 128 + pr)) * 256) + pq * 32;
            uint32_t ds = sb + SB_B + pr * SB_STR + pq * 32;
            CPA16(ds, gs); CPA16(ds + 16, gs + 16);
            CPA_COMMIT();
        }

        for (int ci = 0; ci < 8; ci++) {
            if (ci < 7) {
                int cn = ci + 1;
                const __nv_bfloat16* src = (cn < 4) ? g_eh : g_el;
                int kb64 = (cn & 3) * 64;
                const char* gs = (const char*)(src + ((size_t)(nt * 128 + pr)) * 256 + kb64) + pq * 32;
                uint32_t ds = sb + SB_B + (cn % 3) * SB_SZ + pr * SB_STR + pq * 32;
                CPA16(ds, gs); CPA16(ds + 16, gs + 16);
                CPA_COMMIT();
                asm volatile("cp.async.wait_group 1;" ::: "memory");
            } else {
                asm volatile("cp.async.wait_group 0;" ::: "memory");
            }
            __syncthreads();  // sole barrier per chunk (3-buffer ring covers WAR hazard)

            int kb = (ci & 3) * 64;
            uint32_t bbase = sb + SB_B + (ci % 3) * SB_SZ;
            int nterms = (ci < 4) ? 2 : 1;
#pragma unroll
            for (int kk = 0; kk < 4; kk++) {
                uint32_t b[2][4];
#pragma unroll
                for (int p = 0; p < 2; p++) {
                    uint32_t bd = bbase + (uint32_t)(wn * 32 + p * 16 + b_nof) * SB_STR
                                + (uint32_t)(kk * 16 + b_kof) * 2u;
                    LDSM_X4(b[p][0], b[p][1], b[p][2], b[p][3], bd);
                }
                for (int term = 0; term < nterms; term++) {
                    uint32_t abase = sb + (term ? SA_L : SA_H);
                    uint32_t a[2][4];
#pragma unroll
                    for (int i = 0; i < 2; i++) {
                        uint32_t ad = abase + (uint32_t)(wm * 32 + i * 16 + a_row) * 528u
                                    + (uint32_t)(kb + kk * 16 + a_kof) * 2u;
                        LDSM_X4(a[i][0], a[i][1], a[i][2], a[i][3], ad);
                    }
#pragma unroll
                    for (int i = 0; i < 2; i++) {
                        MMA16816(acc[i][0], a[i][0], a[i][1], a[i][2], a[i][3], b[0][0], b[0][1]);
                        MMA16816(acc[i][1], a[i][0], a[i][1], a[i][2], a[i][3], b[0][2], b[0][3]);
                        MMA16816(acc[i][2], a[i][0], a[i][1], a[i][2], a[i][3], b[1][0], b[1][1]);
                        MMA16816(acc[i][3], a[i][0], a[i][1], a[i][2], a[i][3], b[1][2], b[1][3]);
                    }
                }
            }
        }

        // ---- epilogue: distances + running top-2 (reference rounding kept) ----
#pragma unroll
        for (int i = 0; i < 2; i++)
#pragma unroll
            for (int nf = 0; nf < 4; nf++) {
                int cb = wn * 32 + nf * 8 + (lane & 3) * 2;
                float en0 = s_en[cb], en1 = s_en[cb + 1];
                int k0 = nt * 128 + cb;
                int s0 = i * 2, s1 = i * 2 + 1;
                float d;
                d = (xn4[s0] + en0) - 2.0f * acc[i][nf][0];
                UPD2(d, k0,     b1v[s0], b1i[s0], b2v[s0], b2i[s0]);
                d = (xn4[s0] + en1) - 2.0f * acc[i][nf][1];
                UPD2(d, k0 + 1, b1v[s0], b1i[s0], b2v[s0], b2i[s0]);
                d = (xn4[s1] + en0) - 2.0f * acc[i][nf][2];
                UPD2(d, k0,     b1v[s1], b1i[s1], b2v[s1], b2i[s1]);
                d = (xn4[s1] + en1) - 2.0f * acc[i][nf][3];
                UPD2(d, k0 + 1, b1v[s1], b1i[s1], b2v[s1], b2i[s1]);
            }
        __syncthreads();  // epilogue done before next nt overwrites s_en
    }

    // ---- cross-lane merge (4 lanes share a row): merge top-2 sets ----
#pragma unroll
    for (int off = 1; off <= 2; off <<= 1)
#pragma unroll
        for (int idx = 0; idx < 4; idx++) {
            float o1v = __shfl_xor_sync(0xffffffffu, b1v[idx], off);
            int   o1i = __shfl_xor_sync(0xffffffffu, b1i[idx], off);
            float o2v = __shfl_xor_sync(0xffffffffu, b2v[idx], off);
            int   o2i = __shfl_xor_sync(0xffffffffu, b2i[idx], off);
            UPD2(o1v, o1i, b1v[idx], b1i[idx], b2v[idx], b2i[idx]);
            UPD2(o2v, o2i, b1v[idx], b1i[idx], b2v[idx], b2i[idx]);
        }
    float* sv1 = (float*)(smem + S_B1);
    int*   si1 = (int*)(smem + S_I1);
    float* sv2 = (float*)(smem + S_B2);
    int*   si2 = (int*)(smem + S_I2);
    if ((lane & 3) == 0) {
#pragma unroll
        for (int idx = 0; idx < 4; idx++) {
            int i = idx >> 1, j = idx & 1;
            int row = wm * 32 + i * 16 + j * 8 + (lane >> 2);
            sv1[row * 4 + wn] = b1v[idx]; si1[row * 4 + wn] = b1i[idx];
            sv2[row * 4 + wn] = b2v[idx]; si2[row * 4 + wn] = b2i[idx];
        }
    }
    __syncthreads();
    if (tid < 128) {
        float bv = sv1[tid * 4], b2 = sv2[tid * 4];
        int bk = si1[tid * 4], k2 = si2[tid * 4];
#pragma unroll
        for (int w = 1; w < 4; w++) {
            float o1 = sv1[tid * 4 + w], o2 = sv2[tid * 4 + w];
            int p1 = si1[tid * 4 + w], p2 = si2[tid * 4 + w];
            UPD2(o1, p1, bv, bk, b2, k2);
            UPD2(o2, p2, bv, bk, b2, k2);
        }
        int n = rowbase + tid;
        // near-tie: exact fp32 rescore of the two candidates (reference semantics)
        if (b2 - bv <= GAP_EPS) {
            float xn = g_xnorm[n];
            float d1 = exact_dist(f4, (const float4*)emb, n, bk, xn);
            float d2 = exact_dist(f4, (const float4*)emb, n, k2, xn);
            if (d2 < d1 || (d2 == d1 && k2 < bk)) bk = k2;
        }
        g_idx[n] = bk;
        atomicAdd(&g_counts[bk], 1);
        if (out_idx) out_idx[n] = (float)bk;
    }
}

// ======================= EMA / losses (as R8) =======================
__global__ void k_scan(const float* __restrict__ ema_cs, float* __restrict__ out_ncs) {
    __shared__ int   sc[KK];
    __shared__ float red[KK];
    int t = threadIdx.x;
    int c = g_counts[t];
    float ncs = DECAYV * ema_cs[t] + (1.0f - DECAYV) * (float)c;
    g_ncs[t] = ncs;
    if (out_ncs) out_ncs[t] = ncs;
    red[t] = ncs;
    __syncthreads();
#pragma unroll
    for (int o = 512; o; o >>= 1) {
        if (t < o) red[t] += red[t + o];
        __syncthreads();
    }
    if (t == 0) g_ntotal = red[0] + EPSV;
    sc[t] = c;
    __syncthreads();
    for (int o = 1; o < KK; o <<= 1) {
        int u = (t >= o) ? sc[t - o] : 0;
        __syncthreads();
        sc[t] += u;
        __syncthreads();
    }
    g_offsets[t] = sc[t] - c;
}

__global__ __launch_bounds__(256) void k_scatter() {
    int n = blockIdx.x * 256 + threadIdx.x;
    int k = g_idx[n];
    int pos = atomicAdd(&g_cursor[k], 1);
    g_bucket[g_offsets[k] + pos] = n;
}

__global__ __launch_bounds__(256) void k_codesum(const float* __restrict__ flat,
                                                 const float* __restrict__ ema_avg,
                                                 float* __restrict__ out_ne,
                                                 float* __restrict__ out_nea) {
    __shared__ int sn[256];
    int k = blockIdx.x;
    int d = threadIdx.x;
    int start = g_offsets[k];
    int cnt = g_counts[k];
    float s = 0.f;
    for (int base = 0; base < cnt; base += 256) {
        int m = min(256, cnt - base);
        __syncthreads();
        if (d < m) sn[d] = g_bucket[start + base + d];
        __syncthreads();
        int t = 0;
        for (; t + 4 <= m; t += 4) {
            float v0 = flat[(size_t)sn[t + 0] * DD + d];
            float v1 = flat[(size_t)sn[t + 1] * DD + d];
            float v2 = flat[(size_t)sn[t + 2] * DD + d];
            float v3 = flat[(size_t)sn[t + 3] * DD + d];
            s += ((v0 + v1) + (v2 + v3));
        }
        for (; t < m; t++) s += flat[(size_t)sn[t] * DD + d];
    }
    float navg = DECAYV * ema_avg[(size_t)k * DD + d] + (1.0f - DECAYV) * s;
    if (out_nea) out_nea[(size_t)k * DD + d] = navg;
    float cs = (g_ncs[k] + EPSV) / g_ntotal;
    if (out_ne) out_ne[(size_t)k * DD + d] = navg / cs;
}

__global__ __launch_bounds__(256) void k_quant(const float* __restrict__ flat,
                                               const float* __restrict__ emb,
                                               float* __restrict__ out_q) {
    int tid = threadIdx.x;
    int c = tid & 63;
    int rs = tid >> 6;
    int base = blockIdx.x * 64;
    const float4* f4 = (const float4*)flat;
    const float4* e4 = (const float4*)emb;
    float4* o4 = (float4*)out_q;
    float acc = 0.f;
#pragma unroll 4
    for (int it = 0; it < 16; it++) {
        int n = base + it * 4 + rs;
        int k = g_idx[n];
        float4 x = f4[(size_t)n * 64 + c];
        float4 e = e4[(size_t)k * 64 + c];
        float dx = e.x - x.x, dy = e.y - x.y, dz = e.z - x.z, dw = e.w - x.w;
        acc += dx * dx + dy * dy + dz * dz + dw * dw;
        if (out_q) {
            float4 st;
            st.x = x.x + dx; st.y = x.y + dy; st.z = x.z + dz; st.w = x.w + dw;
            o4[(size_t)n * 64 + c] = st;
        }
    }
    __shared__ float red[256];
    red[tid] = acc;
    __syncthreads();
#pragma unroll
    for (int o = 128; o; o >>= 1) {
        if (tid < o) red[tid] += red[tid + o];
        __syncthreads();
    }
    if (tid == 0) atomicAdd(&g_mse, red[0]);
}

__global__ __launch_bounds__(256) void k_ortho(const float* __restrict__ emb) {
    __shared__ float Ei[32][65];
    __shared__ float Ej[32][65];
    int bi = blockIdx.x >> 5;
    int bj = blockIdx.x & 31;
    int tid = threadIdx.x;
    int tx = tid & 15, ty = tid >> 4;
    const float4* e4 = (const float4*)emb;
    float acc[2][2] = {{0.f, 0.f}, {0.f, 0.f}};
    for (int dc = 0; dc < 4; dc++) {
#pragma unroll
        for (int s = 0; s < 2; s++) {
            int i = s * 256 + tid;
            int r = i >> 4, c = i & 15;
            float4 va = e4[(size_t)(bi * 32 + r) * 64 + dc * 16 + c];
            Ei[r][c * 4 + 0] = va.x; Ei[r][c * 4 + 1] = va.y;
            Ei[r][c * 4 + 2] = va.z; Ei[r][c * 4 + 3] = va.w;
            float4 vb = e4[(size_t)(bj * 32 + r) * 64 + dc * 16 + c];
            Ej[r][c * 4 + 0] = vb.x; Ej[r][c * 4 + 1] = vb.y;
            Ej[r][c * 4 + 2] = vb.z; Ej[r][c * 4 + 3] = vb.w;
        }
        __syncthreads();
#pragma unroll 8
        for (int d = 0; d < 64; d++) {
            float a0 = Ei[ty * 2 + 0][d], a1 = Ei[ty * 2 + 1][d];
            float b0 = Ej[tx * 2 + 0][d], b1 = Ej[tx * 2 + 1][d];
            acc[0][0] += a0 * b0; acc[0][1] += a0 * b1;
            acc[1][0] += a1 * b0; acc[1][1] += a1 * b1;
        }
        __syncthreads();
    }
    float s = 0.f;
#pragma unroll
    for (int ii = 0; ii < 2; ii++)
#pragma unroll
        for (int jj = 0; jj < 2; jj++) {
            int gi = bi * 32 + ty * 2 + ii;
            int gj = bj * 32 + tx * 2 + jj;
            if (gi != gj) s += acc[ii][jj] * acc[ii][jj];
        }
    __shared__ float red[256];
    red[tid] = s;
    __syncthreads();
#pragma unroll
    for (int o = 128; o; o >>= 1) {
        if (tid < o) red[tid] += red[tid + o];
        __syncthreads();
    }
    if (tid == 0) atomicAdd(&g_ortho, red[0]);
}

__global__ void k_loss(float* __restrict__ out_loss) {
    float mse_mean = g_mse / 33554432.0f;
    float loss = mse_mean + 0.25f * mse_mean + 0.09f * sqrtf(g_ortho);
    if (out_loss) *out_loss = loss;
}

// ---------------------------------------------------------------------------
extern "C" void kernel_launch(void* const* d_in, const int* in_sizes, int n_in,
                              void* d_out, int out_size) {
    const float* flat    = (const float*)d_in[0];
    const float* emb     = (const float*)d_in[1];
    const float* ema_cs  = (const float*)d_in[2];
    const float* ema_avg = (const float*)d_in[3];
    float* out = (float*)d_out;

    const int FULL = 34210817;
    bool isfull = (out_size >= FULL);
    float* out_q    = out;
    float* out_loss = isfull ? out + 33554432 : nullptr;
    float* out_idx  = isfull ? out + 33554433 : nullptr;
    float* out_ne   = isfull ? out + 33685505 : nullptr;
    float* out_ncs  = isfull ? out + 33947649 : nullptr;
    float* out_nea  = isfull ? out + 33948673 : nullptr;

    cudaFuncSetAttribute(k_argmin_mma, cudaFuncAttributeMaxDynamicSharedMemorySize, SMEM_TOTAL);

    k_init<<<4, 256>>>();
    k_embsplit<<<KK * DD / 4 / 256, 256>>>(emb);
    k_norms<<<(NN + KK) / 8, 256>>>(flat, emb);
    k_argmin_mma<<<NN / 128, 512, SMEM_TOTAL>>>(flat, emb, out_idx);
    k_scan<<<1, 1024>>>(ema_cs, out_ncs);
    k_scatter<<<NN / 256, 256>>>();
    k_codesum<<<KK, 256>>>(flat, ema_avg, out_ne, out_nea);
    k_quant<<<NN / 64, 256>>>(flat, emb, out_q);
    k_ortho<<<1024, 256>>>(emb);
    k_loss<<<1, 1>>>(out_loss);
}